// round 6
// baseline (speedup 1.0000x reference)
#include <cuda_runtime.h>
#include <cuda_fp16.h>
#include <cstdint>

#define NCHUNK 105
#define HID    512
#define NROWS  220000
#define KD     512

// ---- big GEMM ----
#define MT     256            // rows per CTA (16 warps x 16)
#define NTILES 14             // n8 tiles (112 cols, 105 used)
#define KSTEPS 32             // k16 steps
#define BSROW  480            // bytes per Bs row (224 used + 16 pad) -> conflict-free
#define BS_SMEM (256 * BSROW) // 122880

// ---- fused MLP ----
#define MLP_BLOCKS 64
#define CT       35           // chunk tile (105 = 3*35)
#define MLP_SMEM (CT * HID * 4)  // 71680

// ---------------- device scratch ----------------
__device__ float  g_h1[NCHUNK * HID];
__device__ float  g_h2[NCHUNK * HID];
__device__ __half g_Bp[256 * 224];   // permuted fp16 B image; pad cols stay 0
__device__ volatile unsigned long long g_barctr;

// ---------------- PTX helpers ----------------
__device__ __forceinline__ uint32_t smem_u32_of(const void* p) {
    uint32_t a;
    asm("{ .reg .u64 t; cvta.to.shared.u64 t, %1; cvt.u32.u64 %0, t; }" : "=r"(a) : "l"(p));
    return a;
}
__device__ __forceinline__ void mma16816(float* d, const uint32_t* a, const uint32_t* b) {
    asm volatile(
        "mma.sync.aligned.m16n8k16.row.col.f32.f16.f16.f32 "
        "{%0,%1,%2,%3}, {%4,%5,%6,%7}, {%8,%9}, {%0,%1,%2,%3};"
        : "+f"(d[0]), "+f"(d[1]), "+f"(d[2]), "+f"(d[3])
        : "r"(a[0]), "r"(a[1]), "r"(a[2]), "r"(a[3]), "r"(b[0]), "r"(b[1]));
}
__device__ __forceinline__ uint32_t cvt2(float lo, float hi) {
    __half2 h = __floats2half2_rn(lo, hi);
    return *reinterpret_cast<uint32_t*>(&h);
}
__device__ __forceinline__ uint32_t ldsb32(uint32_t addr) {
    uint32_t v;
    asm volatile("ld.shared.b32 %0, [%1];" : "=r"(v) : "r"(addr));
    return v;
}

// ---------------- monotone grid barrier (graph-replay safe) --------------
__device__ __forceinline__ void grid_barrier(int tid) {
    __threadfence();
    __syncthreads();
    if (tid == 0) {
        unsigned long long t =
            atomicAdd((unsigned long long*)&g_barctr, 1ULL);
        unsigned long long target =
            (t / MLP_BLOCKS + 1ULL) * (unsigned long long)MLP_BLOCKS;
        while (g_barctr < target) { }
    }
    __syncthreads();
    __threadfence();
}

// ---------------- fused MLP: build + 3 layers, one kernel ----------------
// 64 blocks x 256 thr; warp = one output j per layer (64*8 = 512 j).
__global__ __launch_bounds__(256)
void mlp_kernel(const float* __restrict__ preference,
                const float* __restrict__ pref_emb,
                const float* __restrict__ chunk_emb,
                const float* __restrict__ W1, const float* __restrict__ b1,
                const float* __restrict__ W2, const float* __restrict__ b2,
                const float* __restrict__ W3, const float* __restrict__ b3) {
    extern __shared__ float dsm[];
    __shared__ float pe[64];
    int tid = threadIdx.x, lane = tid & 31, wid = tid >> 5;
    int j = blockIdx.x * 8 + wid;

    if (tid < 64)
        pe[tid] = preference[0] * pref_emb[tid] + preference[1] * pref_emb[64 + tid];
    __syncthreads();

    // ---- layer 1 (in=128) ----
    {
        float4 w = reinterpret_cast<const float4*>(W1)[j * 32 + lane];
        float bj = b1[j];
        for (int ct = 0; ct < 3; ct++) {
            int cb = ct * CT;
            for (int i = tid; i < CT * 128; i += 256) {
                int c = i >> 7, k = i & 127;
                dsm[i] = (k < 64) ? pe[k] : chunk_emb[(cb + c) * 64 + (k - 64)];
            }
            __syncthreads();
            const float4* xt = reinterpret_cast<const float4*>(dsm);
            for (int c = 0; c < CT; c++) {
                float4 x = xt[c * 32 + lane];
                float v = w.x * x.x + w.y * x.y + w.z * x.z + w.w * x.w;
#pragma unroll
                for (int o = 16; o; o >>= 1) v += __shfl_down_sync(~0u, v, o);
                if (lane == 0)
                    g_h1[(cb + c) * HID + j] = fmaxf(v + bj, 0.f);
            }
            __syncthreads();
        }
    }
    grid_barrier(tid);

    // ---- layer 2 (in=512) ----
    {
        float4 w[4];
#pragma unroll
        for (int i = 0; i < 4; i++)
            w[i] = reinterpret_cast<const float4*>(W2)[j * 128 + i * 32 + lane];
        float bj = b2[j];
        for (int ct = 0; ct < 3; ct++) {
            int cb = ct * CT;
            for (int i = tid; i < CT * 128; i += 256)
                reinterpret_cast<float4*>(dsm)[i] =
                    reinterpret_cast<const float4*>(g_h1)[cb * 128 + i];
            __syncthreads();
            const float4* ht = reinterpret_cast<const float4*>(dsm);
            for (int c = 0; c < CT; c++) {
                float v = 0.f;
#pragma unroll
                for (int i = 0; i < 4; i++) {
                    float4 h = ht[c * 128 + i * 32 + lane];
                    v += w[i].x * h.x + w[i].y * h.y + w[i].z * h.z + w[i].w * h.w;
                }
#pragma unroll
                for (int o = 16; o; o >>= 1) v += __shfl_down_sync(~0u, v, o);
                if (lane == 0)
                    g_h2[(cb + c) * HID + j] = fmaxf(v + bj, 0.f);
            }
            __syncthreads();
        }
    }
    grid_barrier(tid);

    // ---- layer 3 (in=512, no relu) -> permuted fp16 B image ----
    {
        float4 w[4];
#pragma unroll
        for (int i = 0; i < 4; i++)
            w[i] = reinterpret_cast<const float4*>(W3)[j * 128 + i * 32 + lane];
        float bj = b3[j];
        // perm: actual k=j -> tile t=j>>4, a=j&15: q=a>>2, h=(a>>1)&1, b=a&1
        int a = j & 15;
        int row = (j >> 4) * 8 + (a >> 2) + 4 * ((a >> 1) & 1);
        int bsel = a & 1;
        for (int ct = 0; ct < 3; ct++) {
            int cb = ct * CT;
            for (int i = tid; i < CT * 128; i += 256)
                reinterpret_cast<float4*>(dsm)[i] =
                    reinterpret_cast<const float4*>(g_h2)[cb * 128 + i];
            __syncthreads();
            const float4* ht = reinterpret_cast<const float4*>(dsm);
            for (int c = 0; c < CT; c++) {
                float v = 0.f;
#pragma unroll
                for (int i = 0; i < 4; i++) {
                    float4 h = ht[c * 128 + i * 32 + lane];
                    v += w[i].x * h.x + w[i].y * h.y + w[i].z * h.z + w[i].w * h.w;
                }
#pragma unroll
                for (int o = 16; o; o >>= 1) v += __shfl_down_sync(~0u, v, o);
                if (lane == 0)
                    g_Bp[row * 224 + (cb + c) * 2 + bsel] = __float2half_rn(v + bj);
            }
            __syncthreads();
        }
    }
}

// ---------------- big GEMM: out[n][m] = ws[m] . rep[n] -------------------
// 512 thr (16 warps), warp tile m16 x n112, A direct-LDG (k-permuted),
// B image resident in SMEM. No mainloop syncs.
__global__ __launch_bounds__(512)
void big_kernel(const float* __restrict__ ws, float* __restrict__ out) {
    extern __shared__ char smem[];
    const uint32_t sb = smem_u32_of(smem);
    const int tid = threadIdx.x, lane = tid & 31, wid = tid >> 5;

    // load permuted B image (256 rows x 224 halves) with 480B row stride
    {
        const float4* src = reinterpret_cast<const float4*>(g_Bp);
        for (int i = tid; i < 256 * 28; i += 512) {
            int r = i / 28, q = i - r * 28;
            *reinterpret_cast<float4*>(smem + r * BSROW + q * 16) = src[i];
        }
    }
    __syncthreads();

    const long long mwbase = (long long)blockIdx.x * MT + wid * 16;
    long long r0 = mwbase + (lane >> 2);
    long long r1 = r0 + 8;
    long long r0c = r0 < NROWS ? r0 : NROWS - 1;
    long long r1c = r1 < NROWS ? r1 : NROWS - 1;
    const float4* ap0 = reinterpret_cast<const float4*>(ws) + r0c * (KD / 4) + (lane & 3);
    const float4* ap1 = reinterpret_cast<const float4*>(ws) + r1c * (KD / 4) + (lane & 3);

    // b-frag base: row = t*8 + q (+4), col halfpair n = nt*8 + lane>>2
    const uint32_t bbase = sb + (uint32_t)(lane & 3) * BSROW + (uint32_t)(lane >> 2) * 4;

    float acc[NTILES][4];
#pragma unroll
    for (int i = 0; i < NTILES; i++)
#pragma unroll
        for (int k = 0; k < 4; k++) acc[i][k] = 0.f;

    // 2-deep A prefetch
    float4 pa0[2], pa1[2];
    pa0[0] = ap0[0];      pa1[0] = ap1[0];
    pa0[1] = ap0[4];      pa1[1] = ap1[4];

#pragma unroll 4
    for (int t = 0; t < KSTEPS; t++) {
        float4 ca0 = pa0[t & 1];
        float4 ca1 = pa1[t & 1];
        if (t + 2 < KSTEPS) {
            pa0[t & 1] = ap0[(t + 2) * 4];
            pa1[t & 1] = ap1[(t + 2) * 4];
        }
        uint32_t ar[4];
        ar[0] = cvt2(ca0.x, ca0.y);   // (r , slots 2q,2q+1) = actual 4q,4q+1
        ar[1] = cvt2(ca1.x, ca1.y);   // (r+8, same)
        ar[2] = cvt2(ca0.z, ca0.w);   // (r , slots 2q+8,2q+9) = actual 4q+2,4q+3
        ar[3] = cvt2(ca1.z, ca1.w);
        uint32_t brow = bbase + (uint32_t)t * (8 * BSROW);
#pragma unroll
        for (int nt = 0; nt < NTILES; nt++) {
            uint32_t b[2];
            b[0] = ldsb32(brow + nt * 32);
            b[1] = ldsb32(brow + 4 * BSROW + nt * 32);
            mma16816(acc[nt], ar, b);
        }
    }

    // epilogue
    long long m0 = mwbase + (lane >> 2);
    long long m1 = m0 + 8;
    int nb = 2 * (lane & 3);
#pragma unroll
    for (int nt = 0; nt < NTILES; nt++) {
        int n0 = nt * 8 + nb, n1 = n0 + 1;
        if (m0 < NROWS) {
            if (n0 < NCHUNK) out[(size_t)n0 * NROWS + m0] = acc[nt][0];
            if (n1 < NCHUNK) out[(size_t)n1 * NROWS + m0] = acc[nt][1];
        }
        if (m1 < NROWS) {
            if (n0 < NCHUNK) out[(size_t)n0 * NROWS + m1] = acc[nt][2];
            if (n1 < NCHUNK) out[(size_t)n1 * NROWS + m1] = acc[nt][3];
        }
    }
}

// ---------------------------- launcher -----------------------------------
extern "C" void kernel_launch(void* const* d_in, const int* in_sizes, int n_in,
                              void* d_out, int out_size) {
    const float* preference = (const float*)d_in[0];
    const float* pref_emb   = (const float*)d_in[1];
    const float* chunk_emb  = (const float*)d_in[2];
    const float* W1         = (const float*)d_in[3];
    const float* b1         = (const float*)d_in[4];
    const float* W2         = (const float*)d_in[5];
    const float* b2         = (const float*)d_in[6];
    const float* W3         = (const float*)d_in[7];
    const float* b3         = (const float*)d_in[8];
    const float* ws         = (const float*)d_in[9];
    float* out = (float*)d_out;

    static int attr_done = 0;
    if (!attr_done) {
        cudaFuncSetAttribute(mlp_kernel,
            cudaFuncAttributeMaxDynamicSharedMemorySize, MLP_SMEM);
        cudaFuncSetAttribute(big_kernel,
            cudaFuncAttributeMaxDynamicSharedMemorySize, BS_SMEM);
        attr_done = 1;
    }

    mlp_kernel<<<MLP_BLOCKS, 256, MLP_SMEM>>>(preference, pref_emb, chunk_emb,
                                              W1, b1, W2, b2, W3, b3);

    int nblocks = (NROWS + MT - 1) / MT;   // 860
    big_kernel<<<nblocks, 512, BS_SMEM>>>(ws, out);
}